// round 3
// baseline (speedup 1.0000x reference)
#include <cuda_runtime.h>
#include <math.h>

typedef unsigned long long ull;

// ---------------------------------------------------------------------------
// Problem: agg = segment_sum(edge_attr, edge_index[1], N); h = [x, agg];
// 3x ( h = ssp(layer_norm(h @ W + b, g, be)) ), H = 128.  Output fp32 [N,128].
// ---------------------------------------------------------------------------

#define THREADS 256
#define BM 128
#define IN_STRIDE 260                 // sIn row stride in floats (128*260*4 B)
#define SB_STRIDE 132                 // W chunk row stride
#define SMEM_FLOATS (BM * IN_STRIDE + 32 * SB_STRIDE)
#define SMEM_BYTES (SMEM_FLOATS * 4)  // 150016 B

// scatter accumulator scratch (supports N up to 131072 nodes * 128 feats)
__device__ __align__(16) float g_agg[16 * 1024 * 1024];

// ---------------------------------------------------------------------------
// helpers
// ---------------------------------------------------------------------------
__device__ __forceinline__ ull pack2(float x, float y) {
    ull r;
    asm("mov.b64 %0, {%1, %2};" : "=l"(r) : "f"(x), "f"(y));
    return r;
}
__device__ __forceinline__ void unpack2(ull v, float& x, float& y) {
    asm("mov.b64 {%0, %1}, %2;" : "=f"(x), "=f"(y) : "l"(v));
}
__device__ __forceinline__ void fma2(ull& d, ull a, ull b) {
    asm("fma.rn.f32x2 %0, %1, %2, %0;" : "+l"(d) : "l"(a), "l"(b));
}
// shifted softplus, numerically stable
__device__ __forceinline__ float ssp_f(float x) {
    return fmaxf(x, 0.0f) + log1pf(expf(-fabsf(x))) - 0.69314718055994531f;
}

// ---------------------------------------------------------------------------
// zero the aggregation buffer (n4 float4 elements)
// ---------------------------------------------------------------------------
__global__ void zero_agg_kernel(int n4) {
    float4 z = make_float4(0.f, 0.f, 0.f, 0.f);
    float4* p = (float4*)g_agg;
    for (int i = blockIdx.x * blockDim.x + threadIdx.x; i < n4;
         i += gridDim.x * blockDim.x)
        p[i] = z;
}

// ---------------------------------------------------------------------------
// scatter-add: one thread = one float4 chunk of one edge row.
// A warp covers exactly one edge (32 chunks) -> coalesced loads + RED.128.
// edge_index may be int64 or int32 (JAX x64 ambiguity) -> detect at runtime.
// ---------------------------------------------------------------------------
__global__ void scatter_kernel(const float* __restrict__ ea,
                               const void* __restrict__ ei, int E) {
    const int* pi = (const int*)ei;
    // int64 node indices < 2^31 => every odd 32-bit word of row0 is zero.
    bool is64 = ((pi[1] | pi[3] | pi[5] | pi[7]) == 0);
    const long long* pl = (const long long*)ei;

    long long total = (long long)E * 32;
    const float4* ea4 = (const float4*)ea;
    for (long long i = blockIdx.x * (long long)blockDim.x + threadIdx.x;
         i < total; i += (long long)gridDim.x * blockDim.x) {
        int e = (int)(i >> 5);
        int c = (int)(i & 31);
        int col = is64 ? (int)pl[E + e] : pi[E + e];
        float4 v = ea4[i];
        atomicAdd((float4*)(g_agg + (long long)col * 128 + c * 4), v);
    }
}

// ---------------------------------------------------------------------------
// register-tiled GEMM: C[128m][128n] = sIn[128m][K] @ W[K][128n]
// thread (tx,ty): rows {ty*4+i, 64+ty*4+i}, cols {tx*4+j, 64+tx*4+j}
// acc[i][j] : packed f32x2 col-pairs
// ---------------------------------------------------------------------------
template <int K>
__device__ __forceinline__ void gemm_tile(const float* __restrict__ sIn,
                                          float* __restrict__ sB,
                                          const float* __restrict__ Wg,
                                          ull acc[8][4], int tid, int tx,
                                          int ty) {
#pragma unroll
    for (int i = 0; i < 8; i++)
#pragma unroll
        for (int j = 0; j < 4; j++) acc[i][j] = 0ULL;

    for (int ch = 0; ch < K / 32; ch++) {
        // load 32xK chunk of W into sB
#pragma unroll
        for (int u = 0; u < 4; u++) {
            int idx = tid + 256 * u;   // 0..1023
            int k = idx >> 5;          // 0..31
            int c4 = idx & 31;         // float4 index in row
            ((float4*)(sB + k * SB_STRIDE))[c4] =
                ((const float4*)(Wg + (ch * 32 + k) * 128))[c4];
        }
        __syncthreads();

#pragma unroll 4
        for (int kk = 0; kk < 32; kk++) {
            int kg = ch * 32 + kk;
            float a[8];
#pragma unroll
            for (int i = 0; i < 4; i++) {
                a[i] = sIn[(ty * 4 + i) * IN_STRIDE + kg];
                a[4 + i] = sIn[(64 + ty * 4 + i) * IN_STRIDE + kg];
            }
            float4 bv0 = *(const float4*)(sB + kk * SB_STRIDE + tx * 4);
            float4 bv1 = *(const float4*)(sB + kk * SB_STRIDE + 64 + tx * 4);
            ull b2[4];
            b2[0] = pack2(bv0.x, bv0.y);
            b2[1] = pack2(bv0.z, bv0.w);
            b2[2] = pack2(bv1.x, bv1.y);
            b2[3] = pack2(bv1.z, bv1.w);
#pragma unroll
            for (int i = 0; i < 8; i++) {
                ull a2 = pack2(a[i], a[i]);
#pragma unroll
                for (int j = 0; j < 4; j++) fma2(acc[i][j], a2, b2[j]);
            }
        }
        __syncthreads();
    }
}

// ---------------------------------------------------------------------------
// epilogue: acc + bias -> sIn ; then per-row LayerNorm + ssp.
// gout == nullptr -> write result back into sIn (feeds next layer),
// else write to global output.
// ---------------------------------------------------------------------------
__device__ __forceinline__ void epilogue(float* __restrict__ sIn, ull acc[8][4],
                                         const float* __restrict__ bias,
                                         const float* __restrict__ g,
                                         const float* __restrict__ be, int tid,
                                         int tx, int ty,
                                         float* __restrict__ gout, int base,
                                         int nrows) {
    // store acc (+bias) to sIn[row][col]
#pragma unroll
    for (int i = 0; i < 8; i++) {
        int row = (i < 4) ? (ty * 4 + i) : (64 + ty * 4 + (i - 4));
#pragma unroll
        for (int h = 0; h < 2; h++) {
            float x0, x1, x2, x3;
            unpack2(acc[i][2 * h], x0, x1);
            unpack2(acc[i][2 * h + 1], x2, x3);
            float4 bb = *(const float4*)(bias + h * 64 + tx * 4);
            x0 += bb.x; x1 += bb.y; x2 += bb.z; x3 += bb.w;
            *(float4*)(sIn + row * IN_STRIDE + h * 64 + tx * 4) =
                make_float4(x0, x1, x2, x3);
        }
    }
    __syncthreads();

    // LayerNorm + ssp: 2 threads per row (64 floats each), shfl combine
    int row = tid >> 1;
    int h = tid & 1;
    float* r = sIn + row * IN_STRIDE + h * 64;
    float s = 0.f, sq = 0.f;
#pragma unroll
    for (int q = 0; q < 16; q++) {
        float4 v = ((const float4*)r)[q];
        s += v.x + v.y + v.z + v.w;
        sq += v.x * v.x + v.y * v.y + v.z * v.z + v.w * v.w;
    }
    s += __shfl_xor_sync(0xffffffffu, s, 1);
    sq += __shfl_xor_sync(0xffffffffu, sq, 1);
    float mu = s * (1.0f / 128.0f);
    float var = sq * (1.0f / 128.0f) - mu * mu;
    float rs = rsqrtf(var + 1e-5f);

#pragma unroll
    for (int q = 0; q < 16; q++) {
        float4 v = ((const float4*)r)[q];
        float4 gg = *(const float4*)(g + h * 64 + q * 4);
        float4 bb = *(const float4*)(be + h * 64 + q * 4);
        v.x = ssp_f((v.x - mu) * rs * gg.x + bb.x);
        v.y = ssp_f((v.y - mu) * rs * gg.y + bb.y);
        v.z = ssp_f((v.z - mu) * rs * gg.z + bb.z);
        v.w = ssp_f((v.w - mu) * rs * gg.w + bb.w);
        if (gout) {
            if (row < nrows)
                ((float4*)(gout + (long long)(base + row) * 128 + h * 64))[q] = v;
        } else {
            ((float4*)r)[q] = v;
        }
    }
    // next gemm_tile's post-load __syncthreads orders these writes
}

// ---------------------------------------------------------------------------
// fused 3-layer MLP: one block = 128 nodes
// ---------------------------------------------------------------------------
__global__ __launch_bounds__(THREADS, 1) void mlp_kernel(
    const float* __restrict__ x, float* __restrict__ out, int N,
    const float* __restrict__ W1, const float* __restrict__ b1,
    const float* __restrict__ g1, const float* __restrict__ be1,
    const float* __restrict__ W2, const float* __restrict__ b2,
    const float* __restrict__ g2, const float* __restrict__ be2,
    const float* __restrict__ W3, const float* __restrict__ b3,
    const float* __restrict__ g3, const float* __restrict__ be3) {
    extern __shared__ float sm[];
    float* sIn = sm;                       // [128][260], layer1 uses k<256
    float* sB = sm + BM * IN_STRIDE;       // [32][132]

    int tid = threadIdx.x;
    int tx = tid & 15;
    int ty = tid >> 4;
    int base = blockIdx.x * BM;
    int nrows = min(BM, N - base);

    // load h = [x, agg] into sIn (zero-pad rows beyond nrows)
    for (int idx = tid; idx < BM * 64; idx += THREADS) {
        int m = idx >> 6;
        int q = idx & 63;  // float4 index within 256-wide row
        float4 v = make_float4(0.f, 0.f, 0.f, 0.f);
        if (m < nrows) {
            long long node = base + m;
            v = (q < 32) ? ((const float4*)x)[node * 32 + q]
                         : ((const float4*)g_agg)[node * 32 + (q - 32)];
        }
        *(float4*)(sIn + m * IN_STRIDE + q * 4) = v;
    }
    __syncthreads();

    ull acc[8][4];

    gemm_tile<256>(sIn, sB, W1, acc, tid, tx, ty);
    epilogue(sIn, acc, b1, g1, be1, tid, tx, ty, nullptr, base, nrows);

    gemm_tile<128>(sIn, sB, W2, acc, tid, tx, ty);
    epilogue(sIn, acc, b2, g2, be2, tid, tx, ty, nullptr, base, nrows);

    gemm_tile<128>(sIn, sB, W3, acc, tid, tx, ty);
    epilogue(sIn, acc, b3, g3, be3, tid, tx, ty, out, base, nrows);
}

// ---------------------------------------------------------------------------
// launch
// ---------------------------------------------------------------------------
extern "C" void kernel_launch(void* const* d_in, const int* in_sizes, int n_in,
                              void* d_out, int out_size) {
    const float* x = (const float*)d_in[0];
    const void* ei = d_in[1];
    const float* ea = (const float*)d_in[2];
    const float* W1 = (const float*)d_in[3];
    const float* b1 = (const float*)d_in[4];
    const float* g1 = (const float*)d_in[5];
    const float* be1 = (const float*)d_in[6];
    const float* W2 = (const float*)d_in[7];
    const float* b2 = (const float*)d_in[8];
    const float* g2 = (const float*)d_in[9];
    const float* be2 = (const float*)d_in[10];
    const float* W3 = (const float*)d_in[11];
    const float* b3 = (const float*)d_in[12];
    const float* g3 = (const float*)d_in[13];
    const float* be3 = (const float*)d_in[14];
    float* out = (float*)d_out;

    int N = in_sizes[0] / 128;   // nodes
    int E = in_sizes[2] / 128;   // edges

    cudaFuncSetAttribute(mlp_kernel, cudaFuncAttributeMaxDynamicSharedMemorySize,
                         SMEM_BYTES);

    zero_agg_kernel<<<1184, THREADS>>>(N * 32);
    scatter_kernel<<<1184, THREADS>>>(ea, ei, E);
    mlp_kernel<<<(N + BM - 1) / BM, THREADS, SMEM_BYTES>>>(
        x, out, N, W1, b1, g1, be1, W2, b2, g2, be2, W3, b3, g3, be3);
}

// round 4
// speedup vs baseline: 1.2103x; 1.2103x over previous
#include <cuda_runtime.h>
#include <math.h>

typedef unsigned long long ull;

// ---------------------------------------------------------------------------
// agg = segment_sum(edge_attr, edge_index[1], N); h = [x, agg];
// 3x ( h = ssp(layer_norm(h @ W + b, g, be)) ), H = 128. Output fp32 [N,128].
// ---------------------------------------------------------------------------

#define THREADS 256
#define BM 128
#define IN_STRIDE 260                 // sIn row stride (floats)
#define SB_STRIDE 132                 // W chunk row stride (floats)
#define SB_BUF (32 * SB_STRIDE)       // one W buffer (floats)
#define SMEM_FLOATS (BM * IN_STRIDE + 2 * SB_BUF)
#define SMEM_BYTES (SMEM_FLOATS * 4)  // 166912 B

// scatter accumulator scratch (N up to 131072 nodes * 128 feats)
__device__ __align__(16) float g_agg[16 * 1024 * 1024];

// ---------------------------------------------------------------------------
__device__ __forceinline__ ull pack2(float x, float y) {
    ull r;
    asm("mov.b64 %0, {%1, %2};" : "=l"(r) : "f"(x), "f"(y));
    return r;
}
__device__ __forceinline__ void unpack2(ull v, float& x, float& y) {
    asm("mov.b64 {%0, %1}, %2;" : "=f"(x), "=f"(y) : "l"(v));
}
__device__ __forceinline__ void fma2(ull& d, ull a, ull b) {
    asm("fma.rn.f32x2 %0, %1, %2, %0;" : "+l"(d) : "l"(a), "l"(b));
}
// shifted softplus (stable): max(x,0) + log(1 + exp(-|x|)) - log(2)
__device__ __forceinline__ float ssp_f(float x) {
    float t = __expf(-fabsf(x));
    return fmaxf(x, 0.0f) + __logf(1.0f + t) - 0.69314718055994531f;
}

// ---------------------------------------------------------------------------
// profiling-alignment probe (no-op; shifts ncu -s 5 capture onto mlp_kernel)
// ---------------------------------------------------------------------------
__global__ void probe_kernel() {}

// ---------------------------------------------------------------------------
__global__ void zero_agg_kernel(int n4) {
    float4 z = make_float4(0.f, 0.f, 0.f, 0.f);
    float4* p = (float4*)g_agg;
    for (int i = blockIdx.x * blockDim.x + threadIdx.x; i < n4;
         i += gridDim.x * blockDim.x)
        p[i] = z;
}

// ---------------------------------------------------------------------------
// scatter-add: one warp = one edge. Lane l handles float4 chunk l of the
// 128-float row -> coalesced LDG.128 + one RED.128 per thread.
// edge_index may be int64 or int32 (JAX x64 ambiguity) -> runtime detect.
// ---------------------------------------------------------------------------
__global__ __launch_bounds__(THREADS) void scatter_kernel(
    const float* __restrict__ ea, const void* __restrict__ ei, int E) {
    int e = blockIdx.x * (THREADS / 32) + (threadIdx.x >> 5);
    if (e >= E) return;
    int lane = threadIdx.x & 31;

    int col = 0;
    if (lane == 0) {
        const int* pi = (const int*)ei;
        // int64 indices < 2^31 => odd 32-bit words of row0 are zero
        bool is64 = ((pi[1] | pi[3] | pi[5] | pi[7]) == 0);
        col = is64 ? (int)((const long long*)ei)[E + e] : pi[E + e];
    }
    col = __shfl_sync(0xffffffffu, col, 0);

    float4 v = ((const float4*)ea)[(long long)e * 32 + lane];
    atomicAdd((float4*)(g_agg + (long long)col * 128 + lane * 4), v);
}

// ---------------------------------------------------------------------------
// register-tiled GEMM: C[128m][128n] = sIn[128m][K] @ W[K][128n]
// thread (tx,ty): rows {ty*4+i, 64+ty*4+i}, cols {tx*4..+3, 64+tx*4..+3}
// acc[i][j]: packed f32x2 column pairs. W double-buffered via registers.
// ---------------------------------------------------------------------------
template <int K>
__device__ __forceinline__ void gemm_tile(const float* __restrict__ sIn,
                                          float* __restrict__ sB,
                                          const float* __restrict__ Wg,
                                          ull acc[8][4], int tid, int tx,
                                          int ty) {
#pragma unroll
    for (int i = 0; i < 8; i++)
#pragma unroll
        for (int j = 0; j < 4; j++) acc[i][j] = 0ULL;

    const int NC = K / 32;
    const float4* Wg4 = (const float4*)Wg;
    float4 r[4];

    // preload chunk 0 into buffer 0
#pragma unroll
    for (int u = 0; u < 4; u++) r[u] = Wg4[tid + 256 * u];
#pragma unroll
    for (int u = 0; u < 4; u++) {
        int idx = tid + 256 * u;  // = k*32 + c4
        ((float4*)(sB + (idx >> 5) * SB_STRIDE))[idx & 31] = r[u];
    }
    __syncthreads();

    for (int ch = 0; ch < NC; ch++) {
        if (ch + 1 < NC) {
#pragma unroll
            for (int u = 0; u < 4; u++)
                r[u] = Wg4[(ch + 1) * 1024 + tid + 256 * u];
        }
        const float* wb = sB + (ch & 1) * SB_BUF;

#pragma unroll 8
        for (int kk = 0; kk < 32; kk++) {
            int kg = ch * 32 + kk;
            float a[8];
#pragma unroll
            for (int i = 0; i < 4; i++) {
                a[i] = sIn[(ty * 4 + i) * IN_STRIDE + kg];
                a[4 + i] = sIn[(64 + ty * 4 + i) * IN_STRIDE + kg];
            }
            // B pairs: raw 64-bit loads, no packing needed
            ulonglong2 b01 =
                *(const ulonglong2*)(wb + kk * SB_STRIDE + tx * 4);
            ulonglong2 b23 =
                *(const ulonglong2*)(wb + kk * SB_STRIDE + 64 + tx * 4);
            ull b2[4] = {b01.x, b01.y, b23.x, b23.y};
#pragma unroll
            for (int i = 0; i < 8; i++) {
                ull a2 = pack2(a[i], a[i]);
#pragma unroll
                for (int j = 0; j < 4; j++) fma2(acc[i][j], a2, b2[j]);
            }
        }

        if (ch + 1 < NC) {
            float* wn = sB + ((ch + 1) & 1) * SB_BUF;
#pragma unroll
            for (int u = 0; u < 4; u++) {
                int idx = tid + 256 * u;
                ((float4*)(wn + (idx >> 5) * SB_STRIDE))[idx & 31] = r[u];
            }
            __syncthreads();
        }
    }
}

// ---------------------------------------------------------------------------
// epilogue: acc + bias -> sIn ; per-row LayerNorm + ssp.
// gout == nullptr -> in-place into sIn (feeds next layer), else global out.
// ---------------------------------------------------------------------------
__device__ __forceinline__ void epilogue(float* __restrict__ sIn, ull acc[8][4],
                                         const float* __restrict__ bias,
                                         const float* __restrict__ g,
                                         const float* __restrict__ be, int tid,
                                         int tx, int ty,
                                         float* __restrict__ gout, int base,
                                         int nrows) {
    __syncthreads();  // all warps done reading sIn (last GEMM chunk)
#pragma unroll
    for (int i = 0; i < 8; i++) {
        int row = (i < 4) ? (ty * 4 + i) : (64 + ty * 4 + (i - 4));
#pragma unroll
        for (int h = 0; h < 2; h++) {
            float x0, x1, x2, x3;
            unpack2(acc[i][2 * h], x0, x1);
            unpack2(acc[i][2 * h + 1], x2, x3);
            float4 bb = *(const float4*)(bias + h * 64 + tx * 4);
            *(float4*)(sIn + row * IN_STRIDE + h * 64 + tx * 4) =
                make_float4(x0 + bb.x, x1 + bb.y, x2 + bb.z, x3 + bb.w);
        }
    }
    __syncthreads();

    // LayerNorm + ssp: 2 threads per row, shfl combine
    int row = tid >> 1;
    int h = tid & 1;
    float* r = sIn + row * IN_STRIDE + h * 64;
    float s = 0.f, sq = 0.f;
#pragma unroll
    for (int q = 0; q < 16; q++) {
        float4 v = ((const float4*)r)[q];
        s += v.x + v.y + v.z + v.w;
        sq += v.x * v.x + v.y * v.y + v.z * v.z + v.w * v.w;
    }
    s += __shfl_xor_sync(0xffffffffu, s, 1);
    sq += __shfl_xor_sync(0xffffffffu, sq, 1);
    float mu = s * (1.0f / 128.0f);
    float var = sq * (1.0f / 128.0f) - mu * mu;
    float rs = rsqrtf(var + 1e-5f);

#pragma unroll
    for (int q = 0; q < 16; q++) {
        float4 v = ((const float4*)r)[q];
        float4 gg = *(const float4*)(g + h * 64 + q * 4);
        float4 bb = *(const float4*)(be + h * 64 + q * 4);
        v.x = ssp_f((v.x - mu) * rs * gg.x + bb.x);
        v.y = ssp_f((v.y - mu) * rs * gg.y + bb.y);
        v.z = ssp_f((v.z - mu) * rs * gg.z + bb.z);
        v.w = ssp_f((v.w - mu) * rs * gg.w + bb.w);
        if (gout) {
            if (row < nrows)
                ((float4*)(gout + (long long)(base + row) * 128 + h * 64))[q] = v;
        } else {
            ((float4*)r)[q] = v;
        }
    }
    __syncthreads();
}

// ---------------------------------------------------------------------------
// fused 3-layer MLP: one block = 128 nodes, zero intermediate HBM traffic
// ---------------------------------------------------------------------------
__global__ __launch_bounds__(THREADS, 1) void mlp_kernel(
    const float* __restrict__ x, float* __restrict__ out, int N,
    const float* __restrict__ W1, const float* __restrict__ b1,
    const float* __restrict__ g1, const float* __restrict__ be1,
    const float* __restrict__ W2, const float* __restrict__ b2,
    const float* __restrict__ g2, const float* __restrict__ be2,
    const float* __restrict__ W3, const float* __restrict__ b3,
    const float* __restrict__ g3, const float* __restrict__ be3) {
    extern __shared__ float sm[];
    float* sIn = sm;                  // [128][260]
    float* sB = sm + BM * IN_STRIDE;  // 2 x [32][132]

    int tid = threadIdx.x;
    int tx = tid & 15;
    int ty = tid >> 4;
    int base = blockIdx.x * BM;
    int nrows = min(BM, N - base);

    // load h = [x, agg] (zero-pad rows beyond nrows)
    for (int idx = tid; idx < BM * 64; idx += THREADS) {
        int m = idx >> 6;
        int q = idx & 63;
        float4 v = make_float4(0.f, 0.f, 0.f, 0.f);
        if (m < nrows) {
            long long node = base + m;
            v = (q < 32) ? ((const float4*)x)[node * 32 + q]
                         : ((const float4*)g_agg)[node * 32 + (q - 32)];
        }
        *(float4*)(sIn + m * IN_STRIDE + q * 4) = v;
    }
    __syncthreads();

    ull acc[8][4];

    gemm_tile<256>(sIn, sB, W1, acc, tid, tx, ty);
    epilogue(sIn, acc, b1, g1, be1, tid, tx, ty, nullptr, base, nrows);

    gemm_tile<128>(sIn, sB, W2, acc, tid, tx, ty);
    epilogue(sIn, acc, b2, g2, be2, tid, tx, ty, nullptr, base, nrows);

    gemm_tile<128>(sIn, sB, W3, acc, tid, tx, ty);
    epilogue(sIn, acc, b3, g3, be3, tid, tx, ty, out, base, nrows);
}

// ---------------------------------------------------------------------------
extern "C" void kernel_launch(void* const* d_in, const int* in_sizes, int n_in,
                              void* d_out, int out_size) {
    const float* x = (const float*)d_in[0];
    const void* ei = d_in[1];
    const float* ea = (const float*)d_in[2];
    const float* W1 = (const float*)d_in[3];
    const float* b1 = (const float*)d_in[4];
    const float* g1 = (const float*)d_in[5];
    const float* be1 = (const float*)d_in[6];
    const float* W2 = (const float*)d_in[7];
    const float* b2 = (const float*)d_in[8];
    const float* g2 = (const float*)d_in[9];
    const float* be2 = (const float*)d_in[10];
    const float* W3 = (const float*)d_in[11];
    const float* b3 = (const float*)d_in[12];
    const float* g3 = (const float*)d_in[13];
    const float* be3 = (const float*)d_in[14];
    float* out = (float*)d_out;

    int N = in_sizes[0] / 128;  // nodes
    int E = in_sizes[2] / 128;  // edges

    cudaFuncSetAttribute(mlp_kernel, cudaFuncAttributeMaxDynamicSharedMemorySize,
                         SMEM_BYTES);

    probe_kernel<<<1, 32>>>();  // shifts ncu -s5 capture onto mlp_kernel
    zero_agg_kernel<<<1184, THREADS>>>(N * 32);
    scatter_kernel<<<(E + 7) / 8, THREADS>>>(ea, ei, E);
    mlp_kernel<<<(N + BM - 1) / BM, THREADS, SMEM_BYTES>>>(
        x, out, N, W1, b1, g1, be1, W2, b2, g2, be2, W3, b3, g3, be3);
}